// round 13
// baseline (speedup 1.0000x reference)
#include <cuda_runtime.h>
#include <cuda_fp16.h>
#include <math.h>
#include <stdint.h>

// Problem constants
#define B_    2
#define T_    2048
#define C_    1024
#define H_    16
#define D_    64
#define M_    (B_ * T_)          // 4096
#define QKVN  (3 * H_ * D_)      // 3072

// Scratch (allocation-free rule: device globals) — fp16
__device__ __half g_xh [(size_t)M_ * C_];      // x in fp16
__device__ __half g_wqT[(size_t)QKVN * C_];    // w_qkv^T  [3072,1024]
__device__ __half g_wpT[(size_t)C_ * C_];      // w_proj^T [1024,1024]
__device__ __half g_qkv[(size_t)M_ * QKVN];
__device__ __half g_y  [(size_t)M_ * C_];

// ---------------------------------------------------------------------------
// helpers
// ---------------------------------------------------------------------------
__device__ __forceinline__ uint32_t pack2(float x, float y) {
    __half2 h = __floats2half2_rn(x, y);
    return *reinterpret_cast<uint32_t*>(&h);
}
__device__ __forceinline__ uint32_t hmax2u(uint32_t a, uint32_t b) {
    uint32_t d;
    asm("max.f16x2 %0, %1, %2;" : "=r"(d) : "r"(a), "r"(b));
    return d;
}
__device__ __forceinline__ uint32_t hadd2u(uint32_t a, uint32_t b) {
    uint32_t d;
    asm("add.f16x2 %0, %1, %2;" : "=r"(d) : "r"(a), "r"(b));
    return d;
}
__device__ __forceinline__ uint32_t ex2h2(uint32_t a) {
    uint32_t d;
    asm("ex2.approx.f16x2 %0, %1;" : "=r"(d) : "r"(a));
    return d;
}
__device__ __forceinline__ void mma_f16(float c[4], const uint32_t a[4],
                                        const uint32_t b[2]) {
    asm volatile(
        "mma.sync.aligned.m16n8k16.row.col.f32.f16.f16.f32 "
        "{%0,%1,%2,%3}, {%4,%5,%6,%7}, {%8,%9}, {%0,%1,%2,%3};\n"
        : "+f"(c[0]), "+f"(c[1]), "+f"(c[2]), "+f"(c[3])
        : "r"(a[0]), "r"(a[1]), "r"(a[2]), "r"(a[3]), "r"(b[0]), "r"(b[1]));
}
__device__ __forceinline__ void ldm_x4(uint32_t r[4], uint32_t addr) {
    asm volatile("ldmatrix.sync.aligned.m8n8.x4.shared.b16 {%0,%1,%2,%3}, [%4];"
        : "=r"(r[0]), "=r"(r[1]), "=r"(r[2]), "=r"(r[3]) : "r"(addr));
}
__device__ __forceinline__ void ldm_x4t(uint32_t r[4], uint32_t addr) {
    asm volatile("ldmatrix.sync.aligned.m8n8.x4.trans.shared.b16 {%0,%1,%2,%3}, [%4];"
        : "=r"(r[0]), "=r"(r[1]), "=r"(r[2]), "=r"(r[3]) : "r"(addr));
}
__device__ __forceinline__ void cpa16(uint32_t dst, const void* src) {
    asm volatile("cp.async.cg.shared.global [%0], [%1], 16;\n" :: "r"(dst), "l"(src));
}
#define CP_COMMIT() asm volatile("cp.async.commit_group;" ::: "memory")
#define CP_WAIT0()  asm volatile("cp.async.wait_group 0;"  ::: "memory")
#define CP_WAIT1()  asm volatile("cp.async.wait_group 1;"  ::: "memory")
#define CP_WAIT2()  asm volatile("cp.async.wait_group 2;"  ::: "memory")

// FMA-only exp2 (no MUFU, no F2I): magic-constant round, degree-4 poly.
__device__ __forceinline__ float exp2_fast(float t) {
    t = fmaxf(t, -120.f);
    const float MAGIC = 12582912.f;            // 1.5 * 2^23
    float fr = t + MAGIC;
    float r  = fr - MAGIC;
    float f  = t - r;
    int ri   = __float_as_int(fr) - 0x4B400000;
    float p = fmaf(f, 0.009618129f, 0.055504109f);
    p = fmaf(f, p, 0.240226507f);
    p = fmaf(f, p, 0.693147181f);
    p = fmaf(f, p, 1.0f);
    return __int_as_float(__float_as_int(p) + (ri << 23));
}

// ---------------------------------------------------------------------------
// pre-pass kernels
// ---------------------------------------------------------------------------
__global__ void convert_x(const float* __restrict__ x, __half* __restrict__ xh,
                          int n4) {
    int i = blockIdx.x * blockDim.x + threadIdx.x;
    if (i < n4) {
        float4 v = reinterpret_cast<const float4*>(x)[i];
        reinterpret_cast<uint2*>(xh)[i] = make_uint2(pack2(v.x, v.y), pack2(v.z, v.w));
    }
}
// wt[n][k] = (half) w[k][n];  w: [K,N] fp32 row-major
__global__ void transpose_w(const float* __restrict__ w, __half* __restrict__ wt,
                            int K, int N) {
    __shared__ __half t[32][33];
    const int n0 = blockIdx.x * 32, k0 = blockIdx.y * 32;
    const int tx = threadIdx.x, ty = threadIdx.y;
    #pragma unroll
    for (int j = 0; j < 32; j += 8)
        t[ty + j][tx] = __float2half(w[(size_t)(k0 + ty + j) * N + n0 + tx]);
    __syncthreads();
    #pragma unroll
    for (int j = 0; j < 32; j += 8)
        wt[(size_t)(n0 + ty + j) * K + k0 + tx] = t[tx][ty + j];
}

// ---------------------------------------------------------------------------
// gemm_cp: round-9 known-good.  C[M,N] = A[M,K] @ Bt[N,K]^T, fp16 K-major.
// 128x128 CTA tile, BK=32, 4-stage cp.async, 128 threads = 4 warps (2x2),
// warp tile 64x64.
// ---------------------------------------------------------------------------
#define GSTAGE 20480
#define GEMM_SMEM (4 * GSTAGE)

template <typename TC>
__global__ __launch_bounds__(128, 2) void gemm_cp(
    const __half* __restrict__ A, const __half* __restrict__ Bt,
    TC* __restrict__ Cm, int M, int N, int K)
{
    extern __shared__ __align__(128) char smem[];
    uint32_t sb;
    asm("{ .reg .u64 t; cvta.to.shared.u64 t, %1; cvt.u32.u64 %0, t; }"
        : "=r"(sb) : "l"(smem));

    const int tid  = threadIdx.x;
    const int lane = tid & 31;
    const int warp = tid >> 5;
    const int wm = warp >> 1, wn = warp & 1;
    const int g = lane >> 2, t = lane & 3;
    const int m0 = blockIdx.y * 128;
    const int n0 = blockIdx.x * 128;
    const int nk = K >> 5;

    const __half* Abase = A + (size_t)m0 * K;
    const __half* Bbase = Bt + (size_t)n0 * K;

    auto load_chunk = [&](int c, int s) {
        const uint32_t base = sb + s * GSTAGE;
        const __half* Ac = Abase + (size_t)c * 32;
        const __half* Bc = Bbase + (size_t)c * 32;
        #pragma unroll
        for (int i = 0; i < 8; i++) {
            const int id  = tid + 128 * i;
            const int ab  = id >> 9;
            const int r   = (id >> 2) & 127;
            const int c16 = id & 3;
            const uint32_t off = ab * 10240u + (uint32_t)r * 80 + c16 * 16;
            const __half* src = (ab ? Bc : Ac) + (size_t)r * K + c16 * 8;
            cpa16(base + off, src);
        }
        CP_COMMIT();
    };

    uint32_t aAddr[4], bAddr[4];
    #pragma unroll
    for (int mt = 0; mt < 4; mt++)
        aAddr[mt] = sb + (wm * 64 + mt * 16 + (lane & 15)) * 80
                       + ((lane >> 4) * 8) * 2;
    #pragma unroll
    for (int ntp = 0; ntp < 4; ntp++)
        bAddr[ntp] = sb + 10240
                   + (wn * 64 + ntp * 16 + ((lane >> 4) & 1) * 8 + (lane & 7)) * 80
                   + (((lane >> 3) & 1) * 8) * 2;

    load_chunk(0, 0); load_chunk(1, 1); load_chunk(2, 2);

    float acc[4][8][4];
    #pragma unroll
    for (int mt = 0; mt < 4; mt++)
        #pragma unroll
        for (int nt = 0; nt < 8; nt++)
            #pragma unroll
            for (int j = 0; j < 4; j++) acc[mt][nt][j] = 0.f;

    for (int kt = 0; kt < nk; kt++) {
        const int s = kt & 3;
        if (kt < nk - 2)       CP_WAIT2();
        else if (kt == nk - 2) CP_WAIT1();
        else                   CP_WAIT0();
        __syncthreads();
        if (kt + 3 < nk) load_chunk(kt + 3, (kt + 3) & 3);

        const uint32_t so = (uint32_t)s * GSTAGE;
        #pragma unroll
        for (int kk = 0; kk < 2; kk++) {
            const uint32_t ko = kk * 32;
            uint32_t af[4][4], bf[4][4];
            #pragma unroll
            for (int mt = 0; mt < 4; mt++)
                ldm_x4(af[mt], aAddr[mt] + so + ko);
            #pragma unroll
            for (int ntp = 0; ntp < 4; ntp++)
                ldm_x4(bf[ntp], bAddr[ntp] + so + ko);
            #pragma unroll
            for (int mt = 0; mt < 4; mt++)
                #pragma unroll
                for (int nt = 0; nt < 8; nt++)
                    mma_f16(acc[mt][nt], af[mt], &bf[nt >> 1][(nt & 1) * 2]);
        }
    }

    #pragma unroll
    for (int mt = 0; mt < 4; mt++) {
        const int r0 = m0 + wm * 64 + mt * 16 + g;
        #pragma unroll
        for (int nt = 0; nt < 8; nt++) {
            const int c0 = n0 + wn * 64 + nt * 8 + 2 * t;
            if (sizeof(TC) == 2) {
                *reinterpret_cast<__half2*>((__half*)Cm + (size_t)r0 * N + c0) =
                    __floats2half2_rn(acc[mt][nt][0], acc[mt][nt][1]);
                *reinterpret_cast<__half2*>((__half*)Cm + (size_t)(r0 + 8) * N + c0) =
                    __floats2half2_rn(acc[mt][nt][2], acc[mt][nt][3]);
            } else {
                *reinterpret_cast<float2*>((float*)Cm + (size_t)r0 * N + c0) =
                    make_float2(acc[mt][nt][0], acc[mt][nt][1]);
                *reinterpret_cast<float2*>((float*)Cm + (size_t)(r0 + 8) * N + c0) =
                    make_float2(acc[mt][nt][2], acc[mt][nt][3]);
            }
        }
    }
}

// ---------------------------------------------------------------------------
// attn_f16: software-pipelined flash attention.  S(tile j+1) is computed
// BEFORE softmax(tile j) so the tensor pipe stays busy while the softmax
// ALU/SHFL chain drains (warps issue in order).  BQ=64, BKV=64, 4 warps,
// 4-stage cp.async ring, online softmax (log2 domain, ex2.approx.f16x2),
// per-thread l partials, skip-rescale branch.  3 CTAs/SM.
// ---------------------------------------------------------------------------
#define KVSTR   72
#define KVROWS  64
#define KVTILE  (KVROWS * KVSTR)
#define KVSTAGE_B (2 * KVTILE * 2)      // 18432 bytes per stage (K + V)
#define ATTN_SMEM (4 * KVSTAGE_B)       // 73728

__global__ __launch_bounds__(128, 3) void attn_f16(
    const __half* __restrict__ qkv, const float* __restrict__ sink,
    __half* __restrict__ y)
{
    extern __shared__ __align__(16) __half KV[];

    const int tid  = threadIdx.x;
    const int lane = tid & 31;
    const int warp = tid >> 5;
    const int g = lane >> 2, t = lane & 3;
    const int qt = (int)gridDim.x - 1 - (int)blockIdx.x;   // longest first
    const int bh = blockIdx.y;
    const int b = bh >> 4, h = bh & 15;
    const int q0 = qt * 64;
    const size_t rowbase = (size_t)b * T_;

    const int rg0 = q0 + warp * 16 + g;
    const int rg1 = rg0 + 8;

    // Q fragments, scale = (1/8)*log2(e) folded in (log2-domain scores)
    uint32_t qa[4][4];
    {
        const __half2 sc = __floats2half2_rn(0.18033688f, 0.18033688f);
        const __half2* qp0 = reinterpret_cast<const __half2*>(
            &qkv[(rowbase + rg0) * QKVN + h * D_]);
        const __half2* qp8 = qp0 + (size_t)8 * QKVN / 2;
        #pragma unroll
        for (int ks = 0; ks < 4; ks++) {
            __half2 v0 = __hmul2(qp0[8 * ks + t], sc);
            __half2 v1 = __hmul2(qp8[8 * ks + t], sc);
            __half2 v2 = __hmul2(qp0[8 * ks + t + 4], sc);
            __half2 v3 = __hmul2(qp8[8 * ks + t + 4], sc);
            qa[ks][0] = *reinterpret_cast<uint32_t*>(&v0);
            qa[ks][1] = *reinterpret_cast<uint32_t*>(&v1);
            qa[ks][2] = *reinterpret_cast<uint32_t*>(&v2);
            qa[ks][3] = *reinterpret_cast<uint32_t*>(&v3);
        }
    }

    // ldmatrix base addresses (stage 0)
    uint32_t sbase;
    asm("{ .reg .u64 tt; cvta.to.shared.u64 tt, %1; cvt.u32.u64 %0, tt; }"
        : "=r"(sbase) : "l"(KV));
    uint32_t addrK[4], addrV[4];
    {
        const int kvK = ((lane >> 4) & 1) * 8 + (lane & 7);
        const int dK  = ((lane >> 3) & 1) * 8;
        #pragma unroll
        for (int kg = 0; kg < 4; kg++)
            addrK[kg] = sbase + ((kvK + 16 * kg) * KVSTR + dK) * 2;
        const uint32_t vbase = sbase + KVTILE * 2;
        const int kvV = ((lane >> 3) & 1) * 8 + (lane & 7);
        #pragma unroll
        for (int dtp = 0; dtp < 4; dtp++) {
            const int dV = dtp * 16 + ((lane >> 4) & 1) * 8;
            addrV[dtp] = vbase + (kvV * KVSTR + dV) * 2;
        }
    }

    // KV tile loader: tile j -> stage s (8 x 16B per thread)
    auto load_kv = [&](int j, int s) {
        const uint32_t base = sbase + (uint32_t)s * KVSTAGE_B;
        const int j0 = j * 64;
        #pragma unroll
        for (int i = 0; i < 8; i++) {
            const int id = tid + 128 * i;          // 0..1023
            const int kv = id >> 9;                // 0 = K, 1 = V
            const int r  = (id >> 3) & 63;
            const int c16 = id & 7;
            const size_t src = (rowbase + j0 + r) * QKVN
                             + (size_t)(1 + kv) * H_ * D_ + h * D_ + c16 * 8;
            cpa16(base + kv * (KVTILE * 2) + r * (KVSTR * 2) + c16 * 16,
                  &qkv[src]);
        }
        CP_COMMIT();
    };

    // S (log2 domain) = (Q*scale*log2e) . K^T into given buffer, given stage
    auto compute_S = [&](float (&s)[8][4], int stage) {
        const uint32_t so = (uint32_t)stage * KVSTAGE_B;
        #pragma unroll
        for (int nt = 0; nt < 8; nt++)
            #pragma unroll
            for (int jj = 0; jj < 4; jj++) s[nt][jj] = 0.f;
        #pragma unroll
        for (int ks = 0; ks < 4; ks++) {
            #pragma unroll
            for (int kg = 0; kg < 4; kg++) {
                uint32_t bk[4];
                ldm_x4(bk, addrK[kg] + so + ks * 32);
                mma_f16(s[2 * kg],     qa[ks], &bk[0]);
                mma_f16(s[2 * kg + 1], qa[ks], &bk[2]);
            }
        }
    };

    // online softmax state (log2 domain; sink: m = sink*log2e)
    float m0v = sink[h] * 1.44269504f, m1v = m0v;
    float lp0 = 0.25f, lp1 = 0.25f;     // quad-sum -> sink l contribution = 1
    float oacc[8][4];
    #pragma unroll
    for (int dt = 0; dt < 8; dt++)
        #pragma unroll
        for (int j = 0; j < 4; j++) oacc[dt][j] = 0.f;

    const int ntile = qt + 1;
    float saccA[8][4], saccB[8][4];

    // ---- prologue: fill pipe (empty commit groups keep counting uniform)
    if (ntile >= 3) {
        load_kv(0, 0); load_kv(1, 1); load_kv(2, 2);
        CP_WAIT2();
    } else if (ntile == 2) {
        load_kv(0, 0); load_kv(1, 1); CP_COMMIT();
        CP_WAIT1();
    } else {
        load_kv(0, 0); CP_COMMIT(); CP_COMMIT();
        CP_WAIT0();
    }
    __syncthreads();
    compute_S(saccA, 0);

    // ---- pipelined iteration: S(tile j+1) issued before softmax(tile j)
    auto iter = [&](float (&scur)[8][4], float (&snxt)[8][4], int j) {
        CP_WAIT1();                  // tiles <= j+1 complete
        __syncthreads();
        // prefetch tile j+3 into stage (j+3)&3 (= tile j-1's stage; its
        // readers finished before the barrier above)
        if (j + 3 < ntile) load_kv(j + 3, (j + 3) & 3);
        else               CP_COMMIT();

        // tensor work for the NEXT tile, independent of softmax below
        if (j + 1 < ntile) compute_S(snxt, (j + 1) & 3);

        // ---- softmax on current tile j
        const int j0 = j * 64;
        if (j0 >= q0) {
            #pragma unroll
            for (int nt = 0; nt < 8; nt++) {
                const int cg = j0 + nt * 8 + 2 * t;
                if (cg     > rg0) scur[nt][0] = -1e30f;
                if (cg + 1 > rg0) scur[nt][1] = -1e30f;
                if (cg     > rg1) scur[nt][2] = -1e30f;
                if (cg + 1 > rg1) scur[nt][3] = -1e30f;
            }
        }

        float rmax0 = -1e30f, rmax1 = -1e30f;
        #pragma unroll
        for (int nt = 0; nt < 8; nt++) {
            rmax0 = fmaxf(rmax0, fmaxf(scur[nt][0], scur[nt][1]));
            rmax1 = fmaxf(rmax1, fmaxf(scur[nt][2], scur[nt][3]));
        }
        uint32_t rmx = pack2(rmax0, rmax1);
        rmx = hmax2u(rmx, __shfl_xor_sync(0xffffffffu, rmx, 1));
        rmx = hmax2u(rmx, __shfl_xor_sync(0xffffffffu, rmx, 2));
        const float2 mx = __half22float2(*reinterpret_cast<__half2*>(&rmx));

        const float mn0 = fmaxf(m0v, mx.x);
        const float mn1 = fmaxf(m1v, mx.y);
        if (mn0 > m0v || mn1 > m1v) {
            const float corr0 = exp2_fast(m0v - mn0);
            const float corr1 = exp2_fast(m1v - mn1);
            lp0 *= corr0; lp1 *= corr1;
            #pragma unroll
            for (int dt = 0; dt < 8; dt++) {
                oacc[dt][0] *= corr0; oacc[dt][1] *= corr0;
                oacc[dt][2] *= corr1; oacc[dt][3] *= corr1;
            }
            m0v = mn0; m1v = mn1;
        }

        // P = 2^(S - m) via ex2.approx.f16x2 — results ARE the A-fragments
        uint32_t pa[4][4];
        #pragma unroll
        for (int kg = 0; kg < 4; kg++) {
            #pragma unroll
            for (int nn = 0; nn < 2; nn++) {
                const int nt = kg * 2 + nn;
                pa[kg][nn * 2 + 0] =
                    ex2h2(pack2(scur[nt][0] - m0v, scur[nt][1] - m0v));
                pa[kg][nn * 2 + 1] =
                    ex2h2(pack2(scur[nt][2] - m1v, scur[nt][3] - m1v));
            }
        }

        // lp += balanced HADD2 tree + one fp32 convert per row
        {
            uint32_t a0 = hadd2u(pa[0][0], pa[0][2]);
            uint32_t a1 = hadd2u(pa[1][0], pa[1][2]);
            uint32_t a2 = hadd2u(pa[2][0], pa[2][2]);
            uint32_t a3 = hadd2u(pa[3][0], pa[3][2]);
            uint32_t v0 = hadd2u(hadd2u(a0, a1), hadd2u(a2, a3));
            float2 f0 = __half22float2(*reinterpret_cast<__half2*>(&v0));
            lp0 += f0.x + f0.y;

            uint32_t b0 = hadd2u(pa[0][1], pa[0][3]);
            uint32_t b1 = hadd2u(pa[1][1], pa[1][3]);
            uint32_t b2 = hadd2u(pa[2][1], pa[2][3]);
            uint32_t b3 = hadd2u(pa[3][1], pa[3][3]);
            uint32_t v1 = hadd2u(hadd2u(b0, b1), hadd2u(b2, b3));
            float2 f1 = __half22float2(*reinterpret_cast<__half2*>(&v1));
            lp1 += f1.x + f1.y;
        }

        // ---- O += P . V  (V from stage j&3)
        const uint32_t soV = (uint32_t)(j & 3) * KVSTAGE_B;
        #pragma unroll
        for (int kg = 0; kg < 4; kg++) {
            const uint32_t koff = soV + kg * (16 * KVSTR * 2);
            uint32_t bv[4][4];
            #pragma unroll
            for (int dtp = 0; dtp < 4; dtp++)
                ldm_x4t(bv[dtp], addrV[dtp] + koff);
            #pragma unroll
            for (int dt = 0; dt < 8; dt++)
                mma_f16(oacc[dt], pa[kg], &bv[dt >> 1][(dt & 1) * 2]);
        }
    };

    for (int j = 0; j < ntile; j += 2) {
        iter(saccA, saccB, j);
        if (j + 1 < ntile) iter(saccB, saccA, j + 1);
    }

    // final l reduction (once); sink share exact (scaled through all corrs)
    float l0 = lp0, l1 = lp1;
    l0 += __shfl_xor_sync(0xffffffffu, l0, 1);
    l0 += __shfl_xor_sync(0xffffffffu, l0, 2);
    l1 += __shfl_xor_sync(0xffffffffu, l1, 1);
    l1 += __shfl_xor_sync(0xffffffffu, l1, 2);
    const float inv0 = 1.f / l0, inv1 = 1.f / l1;

    __half2* yp0 = reinterpret_cast<__half2*>(&y[(rowbase + rg0) * C_ + h * D_]);
    __half2* yp1 = reinterpret_cast<__half2*>(&y[(rowbase + rg1) * C_ + h * D_]);
    #pragma unroll
    for (int dt = 0; dt < 8; dt++) {
        yp0[4 * dt + t] = __floats2half2_rn(oacc[dt][0] * inv0, oacc[dt][1] * inv0);
        yp1[4 * dt + t] = __floats2half2_rn(oacc[dt][2] * inv1, oacc[dt][3] * inv1);
    }
}

// ---------------------------------------------------------------------------
extern "C" void kernel_launch(void* const* d_in, const int* in_sizes, int n_in,
                              void* d_out, int out_size)
{
    const float* x      = (const float*)d_in[0];   // [2,2048,1024]
    const float* w_qkv  = (const float*)d_in[1];   // [1024,3072]
    const float* w_proj = (const float*)d_in[2];   // [1024,1024]
    const float* sink   = (const float*)d_in[3];   // [16]
    float* out = (float*)d_out;                    // [4096,1024]

    __half *xh, *wqT, *wpT, *qkv, *yb;
    cudaGetSymbolAddress((void**)&xh,  g_xh);
    cudaGetSymbolAddress((void**)&wqT, g_wqT);
    cudaGetSymbolAddress((void**)&wpT, g_wpT);
    cudaGetSymbolAddress((void**)&qkv, g_qkv);
    cudaGetSymbolAddress((void**)&yb,  g_y);

    cudaFuncSetAttribute(gemm_cp<__half>,
        cudaFuncAttributeMaxDynamicSharedMemorySize, GEMM_SMEM);
    cudaFuncSetAttribute(gemm_cp<float>,
        cudaFuncAttributeMaxDynamicSharedMemorySize, GEMM_SMEM);
    cudaFuncSetAttribute(attn_f16,
        cudaFuncAttributeMaxDynamicSharedMemorySize, ATTN_SMEM);

    convert_x<<<(M_ * C_ / 4 + 255) / 256, 256>>>(x, xh, M_ * C_ / 4);
    transpose_w<<<dim3(QKVN / 32, C_ / 32), dim3(32, 8)>>>(w_qkv, wqT, C_, QKVN);
    transpose_w<<<dim3(C_ / 32, C_ / 32), dim3(32, 8)>>>(w_proj, wpT, C_, C_);

    gemm_cp<__half><<<dim3(QKVN / 128, M_ / 128), 128, GEMM_SMEM>>>(
        xh, wqT, qkv, M_, QKVN, C_);
    attn_f16<<<dim3(T_ / 64, B_ * H_), 128, ATTN_SMEM>>>(qkv, sink, yb);
    gemm_cp<float><<<dim3(C_ / 128, M_ / 128), 128, GEMM_SMEM>>>(
        yb, wpT, out, M_, C_, C_);
}

// round 14
// speedup vs baseline: 1.0196x; 1.0196x over previous
#include <cuda_runtime.h>
#include <cuda_fp16.h>
#include <math.h>
#include <stdint.h>

// Problem constants
#define B_    2
#define T_    2048
#define C_    1024
#define H_    16
#define D_    64
#define M_    (B_ * T_)          // 4096
#define QKVN  (3 * H_ * D_)      // 3072

// Scratch (allocation-free rule: device globals) — fp16
__device__ __half g_xh [(size_t)M_ * C_];      // x in fp16
__device__ __half g_wqT[(size_t)QKVN * C_];    // w_qkv^T  [3072,1024]
__device__ __half g_wpT[(size_t)C_ * C_];      // w_proj^T [1024,1024]
__device__ __half g_qkv[(size_t)M_ * QKVN];
__device__ __half g_y  [(size_t)M_ * C_];

// ---------------------------------------------------------------------------
// helpers
// ---------------------------------------------------------------------------
__device__ __forceinline__ uint32_t pack2(float x, float y) {
    __half2 h = __floats2half2_rn(x, y);
    return *reinterpret_cast<uint32_t*>(&h);
}
__device__ __forceinline__ uint32_t hmax2u(uint32_t a, uint32_t b) {
    uint32_t d;
    asm("max.f16x2 %0, %1, %2;" : "=r"(d) : "r"(a), "r"(b));
    return d;
}
__device__ __forceinline__ uint32_t hadd2u(uint32_t a, uint32_t b) {
    uint32_t d;
    asm("add.f16x2 %0, %1, %2;" : "=r"(d) : "r"(a), "r"(b));
    return d;
}
__device__ __forceinline__ uint32_t ex2h2(uint32_t a) {
    uint32_t d;
    asm("ex2.approx.f16x2 %0, %1;" : "=r"(d) : "r"(a));
    return d;
}
__device__ __forceinline__ void mma_f16(float c[4], const uint32_t a[4],
                                        const uint32_t b[2]) {
    asm volatile(
        "mma.sync.aligned.m16n8k16.row.col.f32.f16.f16.f32 "
        "{%0,%1,%2,%3}, {%4,%5,%6,%7}, {%8,%9}, {%0,%1,%2,%3};\n"
        : "+f"(c[0]), "+f"(c[1]), "+f"(c[2]), "+f"(c[3])
        : "r"(a[0]), "r"(a[1]), "r"(a[2]), "r"(a[3]), "r"(b[0]), "r"(b[1]));
}
__device__ __forceinline__ void ldm_x4(uint32_t r[4], uint32_t addr) {
    asm volatile("ldmatrix.sync.aligned.m8n8.x4.shared.b16 {%0,%1,%2,%3}, [%4];"
        : "=r"(r[0]), "=r"(r[1]), "=r"(r[2]), "=r"(r[3]) : "r"(addr));
}
__device__ __forceinline__ void ldm_x4t(uint32_t r[4], uint32_t addr) {
    asm volatile("ldmatrix.sync.aligned.m8n8.x4.trans.shared.b16 {%0,%1,%2,%3}, [%4];"
        : "=r"(r[0]), "=r"(r[1]), "=r"(r[2]), "=r"(r[3]) : "r"(addr));
}
__device__ __forceinline__ void cpa16(uint32_t dst, const void* src) {
    asm volatile("cp.async.cg.shared.global [%0], [%1], 16;\n" :: "r"(dst), "l"(src));
}
#define CP_COMMIT() asm volatile("cp.async.commit_group;" ::: "memory")
#define CP_WAIT0()  asm volatile("cp.async.wait_group 0;"  ::: "memory")
#define CP_WAIT1()  asm volatile("cp.async.wait_group 1;"  ::: "memory")
#define CP_WAIT2()  asm volatile("cp.async.wait_group 2;"  ::: "memory")

// FMA-only exp2 (no MUFU, no F2I): magic-constant round, degree-4 poly.
__device__ __forceinline__ float exp2_fast(float t) {
    t = fmaxf(t, -120.f);
    const float MAGIC = 12582912.f;            // 1.5 * 2^23
    float fr = t + MAGIC;
    float r  = fr - MAGIC;
    float f  = t - r;
    int ri   = __float_as_int(fr) - 0x4B400000;
    float p = fmaf(f, 0.009618129f, 0.055504109f);
    p = fmaf(f, p, 0.240226507f);
    p = fmaf(f, p, 0.693147181f);
    p = fmaf(f, p, 1.0f);
    return __int_as_float(__float_as_int(p) + (ri << 23));
}

// ---------------------------------------------------------------------------
// pre-pass kernels
// ---------------------------------------------------------------------------
__global__ void convert_x(const float* __restrict__ x, __half* __restrict__ xh,
                          int n4) {
    int i = blockIdx.x * blockDim.x + threadIdx.x;
    if (i < n4) {
        float4 v = reinterpret_cast<const float4*>(x)[i];
        reinterpret_cast<uint2*>(xh)[i] = make_uint2(pack2(v.x, v.y), pack2(v.z, v.w));
    }
}
// wt[n][k] = (half) w[k][n];  w: [K,N] fp32 row-major
__global__ void transpose_w(const float* __restrict__ w, __half* __restrict__ wt,
                            int K, int N) {
    __shared__ __half t[32][33];
    const int n0 = blockIdx.x * 32, k0 = blockIdx.y * 32;
    const int tx = threadIdx.x, ty = threadIdx.y;
    #pragma unroll
    for (int j = 0; j < 32; j += 8)
        t[ty + j][tx] = __float2half(w[(size_t)(k0 + ty + j) * N + n0 + tx]);
    __syncthreads();
    #pragma unroll
    for (int j = 0; j < 32; j += 8)
        wt[(size_t)(n0 + ty + j) * K + k0 + tx] = t[tx][ty + j];
}

// ---------------------------------------------------------------------------
// gemm_cp: round-9 known-good.  C[M,N] = A[M,K] @ Bt[N,K]^T, fp16 K-major.
// 128x128 CTA tile, BK=32, 4-stage cp.async, 128 threads = 4 warps (2x2),
// warp tile 64x64.
// ---------------------------------------------------------------------------
#define GSTAGE 20480
#define GEMM_SMEM (4 * GSTAGE)

template <typename TC>
__global__ __launch_bounds__(128, 2) void gemm_cp(
    const __half* __restrict__ A, const __half* __restrict__ Bt,
    TC* __restrict__ Cm, int M, int N, int K)
{
    extern __shared__ __align__(128) char smem[];
    uint32_t sb;
    asm("{ .reg .u64 t; cvta.to.shared.u64 t, %1; cvt.u32.u64 %0, t; }"
        : "=r"(sb) : "l"(smem));

    const int tid  = threadIdx.x;
    const int lane = tid & 31;
    const int warp = tid >> 5;
    const int wm = warp >> 1, wn = warp & 1;
    const int g = lane >> 2, t = lane & 3;
    const int m0 = blockIdx.y * 128;
    const int n0 = blockIdx.x * 128;
    const int nk = K >> 5;

    const __half* Abase = A + (size_t)m0 * K;
    const __half* Bbase = Bt + (size_t)n0 * K;

    auto load_chunk = [&](int c, int s) {
        const uint32_t base = sb + s * GSTAGE;
        const __half* Ac = Abase + (size_t)c * 32;
        const __half* Bc = Bbase + (size_t)c * 32;
        #pragma unroll
        for (int i = 0; i < 8; i++) {
            const int id  = tid + 128 * i;
            const int ab  = id >> 9;
            const int r   = (id >> 2) & 127;
            const int c16 = id & 3;
            const uint32_t off = ab * 10240u + (uint32_t)r * 80 + c16 * 16;
            const __half* src = (ab ? Bc : Ac) + (size_t)r * K + c16 * 8;
            cpa16(base + off, src);
        }
        CP_COMMIT();
    };

    uint32_t aAddr[4], bAddr[4];
    #pragma unroll
    for (int mt = 0; mt < 4; mt++)
        aAddr[mt] = sb + (wm * 64 + mt * 16 + (lane & 15)) * 80
                       + ((lane >> 4) * 8) * 2;
    #pragma unroll
    for (int ntp = 0; ntp < 4; ntp++)
        bAddr[ntp] = sb + 10240
                   + (wn * 64 + ntp * 16 + ((lane >> 4) & 1) * 8 + (lane & 7)) * 80
                   + (((lane >> 3) & 1) * 8) * 2;

    load_chunk(0, 0); load_chunk(1, 1); load_chunk(2, 2);

    float acc[4][8][4];
    #pragma unroll
    for (int mt = 0; mt < 4; mt++)
        #pragma unroll
        for (int nt = 0; nt < 8; nt++)
            #pragma unroll
            for (int j = 0; j < 4; j++) acc[mt][nt][j] = 0.f;

    for (int kt = 0; kt < nk; kt++) {
        const int s = kt & 3;
        if (kt < nk - 2)       CP_WAIT2();
        else if (kt == nk - 2) CP_WAIT1();
        else                   CP_WAIT0();
        __syncthreads();
        if (kt + 3 < nk) load_chunk(kt + 3, (kt + 3) & 3);

        const uint32_t so = (uint32_t)s * GSTAGE;
        #pragma unroll
        for (int kk = 0; kk < 2; kk++) {
            const uint32_t ko = kk * 32;
            uint32_t af[4][4], bf[4][4];
            #pragma unroll
            for (int mt = 0; mt < 4; mt++)
                ldm_x4(af[mt], aAddr[mt] + so + ko);
            #pragma unroll
            for (int ntp = 0; ntp < 4; ntp++)
                ldm_x4(bf[ntp], bAddr[ntp] + so + ko);
            #pragma unroll
            for (int mt = 0; mt < 4; mt++)
                #pragma unroll
                for (int nt = 0; nt < 8; nt++)
                    mma_f16(acc[mt][nt], af[mt], &bf[nt >> 1][(nt & 1) * 2]);
        }
    }

    #pragma unroll
    for (int mt = 0; mt < 4; mt++) {
        const int r0 = m0 + wm * 64 + mt * 16 + g;
        #pragma unroll
        for (int nt = 0; nt < 8; nt++) {
            const int c0 = n0 + wn * 64 + nt * 8 + 2 * t;
            if (sizeof(TC) == 2) {
                *reinterpret_cast<__half2*>((__half*)Cm + (size_t)r0 * N + c0) =
                    __floats2half2_rn(acc[mt][nt][0], acc[mt][nt][1]);
                *reinterpret_cast<__half2*>((__half*)Cm + (size_t)(r0 + 8) * N + c0) =
                    __floats2half2_rn(acc[mt][nt][2], acc[mt][nt][3]);
            } else {
                *reinterpret_cast<float2*>((float*)Cm + (size_t)r0 * N + c0) =
                    make_float2(acc[mt][nt][0], acc[mt][nt][1]);
                *reinterpret_cast<float2*>((float*)Cm + (size_t)(r0 + 8) * N + c0) =
                    make_float2(acc[mt][nt][2], acc[mt][nt][3]);
            }
        }
    }
}

// ---------------------------------------------------------------------------
// attn_f16: round-12 config (best known) + __launch_bounds__(128, 4) to force
// regs <= 128 -> 4 CTAs/SM (16 warps) instead of a register-file-limited 3.
// BQ=64, BKV=64, 4 warps x 16 rows, 3-stage cp.async ring, online softmax
// (log2 domain, ex2.approx.f16x2, packed fp16x2 max reduce, HADD2 lp tree).
// ---------------------------------------------------------------------------
#define KVSTR   72
#define KVROWS  64
#define KVTILE  (KVROWS * KVSTR)
#define KVSTAGE_B (2 * KVTILE * 2)
#define ATTN_SMEM (3 * KVSTAGE_B)       // 55296

__global__ __launch_bounds__(128, 4) void attn_f16(
    const __half* __restrict__ qkv, const float* __restrict__ sink,
    __half* __restrict__ y)
{
    extern __shared__ __align__(16) __half KV[];

    const int tid  = threadIdx.x;
    const int lane = tid & 31;
    const int warp = tid >> 5;
    const int g = lane >> 2, t = lane & 3;
    const int qt = (int)gridDim.x - 1 - (int)blockIdx.x;   // longest first
    const int bh = blockIdx.y;
    const int b = bh >> 4, h = bh & 15;
    const int q0 = qt * 64;
    const size_t rowbase = (size_t)b * T_;

    const int rg0 = q0 + warp * 16 + g;
    const int rg1 = rg0 + 8;

    // Q fragments, scale = (1/8)*log2(e) folded in (log2-domain scores)
    uint32_t qa[4][4];
    {
        const __half2 sc = __floats2half2_rn(0.18033688f, 0.18033688f);
        const __half2* qp0 = reinterpret_cast<const __half2*>(
            &qkv[(rowbase + rg0) * QKVN + h * D_]);
        const __half2* qp8 = qp0 + (size_t)8 * QKVN / 2;
        #pragma unroll
        for (int ks = 0; ks < 4; ks++) {
            __half2 v0 = __hmul2(qp0[8 * ks + t], sc);
            __half2 v1 = __hmul2(qp8[8 * ks + t], sc);
            __half2 v2 = __hmul2(qp0[8 * ks + t + 4], sc);
            __half2 v3 = __hmul2(qp8[8 * ks + t + 4], sc);
            qa[ks][0] = *reinterpret_cast<uint32_t*>(&v0);
            qa[ks][1] = *reinterpret_cast<uint32_t*>(&v1);
            qa[ks][2] = *reinterpret_cast<uint32_t*>(&v2);
            qa[ks][3] = *reinterpret_cast<uint32_t*>(&v3);
        }
    }

    // ldmatrix base addresses (stage 0)
    uint32_t sbase;
    asm("{ .reg .u64 tt; cvta.to.shared.u64 tt, %1; cvt.u32.u64 %0, tt; }"
        : "=r"(sbase) : "l"(KV));
    uint32_t addrK[4], addrV[4];
    {
        const int kvK = ((lane >> 4) & 1) * 8 + (lane & 7);
        const int dK  = ((lane >> 3) & 1) * 8;
        #pragma unroll
        for (int kg = 0; kg < 4; kg++)
            addrK[kg] = sbase + ((kvK + 16 * kg) * KVSTR + dK) * 2;
        const uint32_t vbase = sbase + KVTILE * 2;
        const int kvV = ((lane >> 3) & 1) * 8 + (lane & 7);
        #pragma unroll
        for (int dtp = 0; dtp < 4; dtp++) {
            const int dV = dtp * 16 + ((lane >> 4) & 1) * 8;
            addrV[dtp] = vbase + (kvV * KVSTR + dV) * 2;
        }
    }

    // KV tile loader: 64 rows x (K+V) = 16KB per stage, 8 x 16B per thread
    auto load_kv = [&](int j, int s) {
        const uint32_t base = sbase + (uint32_t)s * KVSTAGE_B;
        const int j0 = j * 64;
        #pragma unroll
        for (int i = 0; i < 8; i++) {
            const int id = tid + 128 * i;          // 0..1023
            const int kv = id >> 9;                // 0 = K, 1 = V
            const int r  = (id >> 3) & 63;
            const int c16 = id & 7;
            const size_t src = (rowbase + j0 + r) * QKVN
                             + (size_t)(1 + kv) * H_ * D_ + h * D_ + c16 * 8;
            cpa16(base + kv * (KVTILE * 2) + r * (KVSTR * 2) + c16 * 16,
                  &qkv[src]);
        }
        CP_COMMIT();
    };

    // online softmax state (log2 domain; sink: m = sink*log2e)
    float m0v = sink[h] * 1.44269504f, m1v = m0v;
    float lp0 = 0.25f, lp1 = 0.25f;     // quad-sum -> sink l contribution = 1
    float oacc[8][4];
    #pragma unroll
    for (int dt = 0; dt < 8; dt++)
        #pragma unroll
        for (int j = 0; j < 4; j++) oacc[dt][j] = 0.f;

    const int ntile = qt + 1;
    load_kv(0, 0);
    if (ntile > 1) load_kv(1, 1);

    for (int j = 0; j < ntile; j++) {
        const int s = j % 3;
        if (j < ntile - 1) CP_WAIT1(); else CP_WAIT0();
        __syncthreads();
        if (j + 2 < ntile) load_kv(j + 2, (j + 2) % 3);

        const uint32_t so = (uint32_t)s * KVSTAGE_B;

        // S (log2 domain) = (Q*scale*log2e) . K^T   [16 x 64 per warp]
        float sacc[8][4];
        #pragma unroll
        for (int nt = 0; nt < 8; nt++)
            #pragma unroll
            for (int jj = 0; jj < 4; jj++) sacc[nt][jj] = 0.f;
        #pragma unroll
        for (int ks = 0; ks < 4; ks++) {
            #pragma unroll
            for (int kg = 0; kg < 4; kg++) {
                uint32_t bk[4];
                ldm_x4(bk, addrK[kg] + so + ks * 32);
                mma_f16(sacc[2 * kg],     qa[ks], &bk[0]);
                mma_f16(sacc[2 * kg + 1], qa[ks], &bk[2]);
            }
        }

        // causal mask (diagonal tile only)
        const int j0 = j * 64;
        if (j0 >= q0) {
            #pragma unroll
            for (int nt = 0; nt < 8; nt++) {
                const int cg = j0 + nt * 8 + 2 * t;
                if (cg     > rg0) sacc[nt][0] = -1e30f;
                if (cg + 1 > rg0) sacc[nt][1] = -1e30f;
                if (cg     > rg1) sacc[nt][2] = -1e30f;
                if (cg + 1 > rg1) sacc[nt][3] = -1e30f;
            }
        }

        // row maxima: in-thread fp32, quad-reduce as packed fp16x2 (2 shfl)
        float rmax0 = -1e30f, rmax1 = -1e30f;
        #pragma unroll
        for (int nt = 0; nt < 8; nt++) {
            rmax0 = fmaxf(rmax0, fmaxf(sacc[nt][0], sacc[nt][1]));
            rmax1 = fmaxf(rmax1, fmaxf(sacc[nt][2], sacc[nt][3]));
        }
        uint32_t rmx = pack2(rmax0, rmax1);
        rmx = hmax2u(rmx, __shfl_xor_sync(0xffffffffu, rmx, 1));
        rmx = hmax2u(rmx, __shfl_xor_sync(0xffffffffu, rmx, 2));
        const float2 mx = __half22float2(*reinterpret_cast<__half2*>(&rmx));

        const float mn0 = fmaxf(m0v, mx.x);
        const float mn1 = fmaxf(m1v, mx.y);

        // rescale only when the running max increased (quad-uniform branch)
        if (mn0 > m0v || mn1 > m1v) {
            const float corr0 = exp2_fast(m0v - mn0);
            const float corr1 = exp2_fast(m1v - mn1);
            lp0 *= corr0; lp1 *= corr1;
            #pragma unroll
            for (int dt = 0; dt < 8; dt++) {
                oacc[dt][0] *= corr0; oacc[dt][1] *= corr0;
                oacc[dt][2] *= corr1; oacc[dt][3] *= corr1;
            }
            m0v = mn0; m1v = mn1;
        }

        // P = 2^(S - m) via ex2.approx.f16x2 — results are the A-fragments
        uint32_t pa[4][4];
        #pragma unroll
        for (int kg = 0; kg < 4; kg++) {
            #pragma unroll
            for (int nn = 0; nn < 2; nn++) {
                const int nt = kg * 2 + nn;
                pa[kg][nn * 2 + 0] =
                    ex2h2(pack2(sacc[nt][0] - m0v, sacc[nt][1] - m0v));
                pa[kg][nn * 2 + 1] =
                    ex2h2(pack2(sacc[nt][2] - m1v, sacc[nt][3] - m1v));
            }
        }

        // lp += balanced HADD2 tree (3 levels) + one fp32 convert per row
        {
            uint32_t a0 = hadd2u(pa[0][0], pa[0][2]);
            uint32_t a1 = hadd2u(pa[1][0], pa[1][2]);
            uint32_t a2 = hadd2u(pa[2][0], pa[2][2]);
            uint32_t a3 = hadd2u(pa[3][0], pa[3][2]);
            uint32_t v0 = hadd2u(hadd2u(a0, a1), hadd2u(a2, a3));
            float2 f0 = __half22float2(*reinterpret_cast<__half2*>(&v0));
            lp0 += f0.x + f0.y;

            uint32_t b0 = hadd2u(pa[0][1], pa[0][3]);
            uint32_t b1 = hadd2u(pa[1][1], pa[1][3]);
            uint32_t b2 = hadd2u(pa[2][1], pa[2][3]);
            uint32_t b3 = hadd2u(pa[3][1], pa[3][3]);
            uint32_t v1 = hadd2u(hadd2u(b0, b1), hadd2u(b2, b3));
            float2 f1 = __half22float2(*reinterpret_cast<__half2*>(&v1));
            lp1 += f1.x + f1.y;
        }

        // O += P . V
        #pragma unroll
        for (int kg = 0; kg < 4; kg++) {
            const uint32_t koff = so + kg * (16 * KVSTR * 2);
            uint32_t bv[4][4];
            #pragma unroll
            for (int dtp = 0; dtp < 4; dtp++)
                ldm_x4t(bv[dtp], addrV[dtp] + koff);
            #pragma unroll
            for (int dt = 0; dt < 8; dt++)
                mma_f16(oacc[dt], pa[kg], &bv[dt >> 1][(dt & 1) * 2]);
        }
    }

    // final l reduction (once); sink share exact (scaled through all corrs)
    float l0 = lp0, l1 = lp1;
    l0 += __shfl_xor_sync(0xffffffffu, l0, 1);
    l0 += __shfl_xor_sync(0xffffffffu, l0, 2);
    l1 += __shfl_xor_sync(0xffffffffu, l1, 1);
    l1 += __shfl_xor_sync(0xffffffffu, l1, 2);
    const float inv0 = 1.f / l0, inv1 = 1.f / l1;

    __half2* yp0 = reinterpret_cast<__half2*>(&y[(rowbase + rg0) * C_ + h * D_]);
    __half2* yp1 = reinterpret_cast<__half2*>(&y[(rowbase + rg1) * C_ + h * D_]);
    #pragma unroll
    for (int dt = 0; dt < 8; dt++) {
        yp0[4 * dt + t] = __floats2half2_rn(oacc[dt][0] * inv0, oacc[dt][1] * inv0);
        yp1[4 * dt + t] = __floats2half2_rn(oacc[dt][2] * inv1, oacc[dt][3] * inv1);
    }
}

// ---------------------------------------------------------------------------
extern "C" void kernel_launch(void* const* d_in, const int* in_sizes, int n_in,
                              void* d_out, int out_size)
{
    const float* x      = (const float*)d_in[0];   // [2,2048,1024]
    const float* w_qkv  = (const float*)d_in[1];   // [1024,3072]
    const float* w_proj = (const float*)d_in[2];   // [1024,1024]
    const float* sink   = (const float*)d_in[3];   // [16]
    float* out = (float*)d_out;                    // [4096,1024]

    __half *xh, *wqT, *wpT, *qkv, *yb;
    cudaGetSymbolAddress((void**)&xh,  g_xh);
    cudaGetSymbolAddress((void**)&wqT, g_wqT);
    cudaGetSymbolAddress((void**)&wpT, g_wpT);
    cudaGetSymbolAddress((void**)&qkv, g_qkv);
    cudaGetSymbolAddress((void**)&yb,  g_y);

    cudaFuncSetAttribute(gemm_cp<__half>,
        cudaFuncAttributeMaxDynamicSharedMemorySize, GEMM_SMEM);
    cudaFuncSetAttribute(gemm_cp<float>,
        cudaFuncAttributeMaxDynamicSharedMemorySize, GEMM_SMEM);
    cudaFuncSetAttribute(attn_f16,
        cudaFuncAttributeMaxDynamicSharedMemorySize, ATTN_SMEM);

    convert_x<<<(M_ * C_ / 4 + 255) / 256, 256>>>(x, xh, M_ * C_ / 4);
    transpose_w<<<dim3(QKVN / 32, C_ / 32), dim3(32, 8)>>>(w_qkv, wqT, C_, QKVN);
    transpose_w<<<dim3(C_ / 32, C_ / 32), dim3(32, 8)>>>(w_proj, wpT, C_, C_);

    gemm_cp<__half><<<dim3(QKVN / 128, M_ / 128), 128, GEMM_SMEM>>>(
        xh, wqT, qkv, M_, QKVN, C_);
    attn_f16<<<dim3(T_ / 64, B_ * H_), 128, ATTN_SMEM>>>(qkv, sink, yb);
    gemm_cp<float><<<dim3(C_ / 128, M_ / 128), 128, GEMM_SMEM>>>(
        yb, wpT, out, M_, C_, C_);
}

// round 15
// speedup vs baseline: 1.0294x; 1.0095x over previous
#include <cuda_runtime.h>
#include <cuda_fp16.h>
#include <math.h>
#include <stdint.h>

// Problem constants
#define B_    2
#define T_    2048
#define C_    1024
#define H_    16
#define D_    64
#define M_    (B_ * T_)          // 4096
#define QKVN  (3 * H_ * D_)      // 3072

// Scratch (allocation-free rule: device globals) — fp16
__device__ __half g_xh [(size_t)M_ * C_];      // x in fp16
__device__ __half g_wqT[(size_t)QKVN * C_];    // w_qkv^T  [3072,1024]
__device__ __half g_wpT[(size_t)C_ * C_];      // w_proj^T [1024,1024]
__device__ __half g_qkv[(size_t)M_ * QKVN];
__device__ __half g_y  [(size_t)M_ * C_];

// ---------------------------------------------------------------------------
// helpers
// ---------------------------------------------------------------------------
__device__ __forceinline__ uint32_t pack2(float x, float y) {
    __half2 h = __floats2half2_rn(x, y);
    return *reinterpret_cast<uint32_t*>(&h);
}
__device__ __forceinline__ uint32_t hmax2u(uint32_t a, uint32_t b) {
    uint32_t d;
    asm("max.f16x2 %0, %1, %2;" : "=r"(d) : "r"(a), "r"(b));
    return d;
}
__device__ __forceinline__ uint32_t hadd2u(uint32_t a, uint32_t b) {
    uint32_t d;
    asm("add.f16x2 %0, %1, %2;" : "=r"(d) : "r"(a), "r"(b));
    return d;
}
__device__ __forceinline__ uint32_t ex2h2(uint32_t a) {
    uint32_t d;
    asm("ex2.approx.f16x2 %0, %1;" : "=r"(d) : "r"(a));
    return d;
}
__device__ __forceinline__ void mma_f16(float c[4], const uint32_t a[4],
                                        const uint32_t b[2]) {
    asm volatile(
        "mma.sync.aligned.m16n8k16.row.col.f32.f16.f16.f32 "
        "{%0,%1,%2,%3}, {%4,%5,%6,%7}, {%8,%9}, {%0,%1,%2,%3};\n"
        : "+f"(c[0]), "+f"(c[1]), "+f"(c[2]), "+f"(c[3])
        : "r"(a[0]), "r"(a[1]), "r"(a[2]), "r"(a[3]), "r"(b[0]), "r"(b[1]));
}
__device__ __forceinline__ void ldm_x4(uint32_t r[4], uint32_t addr) {
    asm volatile("ldmatrix.sync.aligned.m8n8.x4.shared.b16 {%0,%1,%2,%3}, [%4];"
        : "=r"(r[0]), "=r"(r[1]), "=r"(r[2]), "=r"(r[3]) : "r"(addr));
}
__device__ __forceinline__ void ldm_x4t(uint32_t r[4], uint32_t addr) {
    asm volatile("ldmatrix.sync.aligned.m8n8.x4.trans.shared.b16 {%0,%1,%2,%3}, [%4];"
        : "=r"(r[0]), "=r"(r[1]), "=r"(r[2]), "=r"(r[3]) : "r"(addr));
}
__device__ __forceinline__ void cpa16(uint32_t dst, const void* src) {
    asm volatile("cp.async.cg.shared.global [%0], [%1], 16;\n" :: "r"(dst), "l"(src));
}
#define CP_COMMIT() asm volatile("cp.async.commit_group;" ::: "memory")
#define CP_WAIT0()  asm volatile("cp.async.wait_group 0;"  ::: "memory")
#define CP_WAIT1()  asm volatile("cp.async.wait_group 1;"  ::: "memory")
#define CP_WAIT2()  asm volatile("cp.async.wait_group 2;"  ::: "memory")

// FMA-only exp2 (no MUFU, no F2I): magic-constant round, degree-4 poly.
__device__ __forceinline__ float exp2_fast(float t) {
    t = fmaxf(t, -120.f);
    const float MAGIC = 12582912.f;            // 1.5 * 2^23
    float fr = t + MAGIC;
    float r  = fr - MAGIC;
    float f  = t - r;
    int ri   = __float_as_int(fr) - 0x4B400000;
    float p = fmaf(f, 0.009618129f, 0.055504109f);
    p = fmaf(f, p, 0.240226507f);
    p = fmaf(f, p, 0.693147181f);
    p = fmaf(f, p, 1.0f);
    return __int_as_float(__float_as_int(p) + (ri << 23));
}

// ---------------------------------------------------------------------------
// pre-pass kernels
// ---------------------------------------------------------------------------
__global__ void convert_x(const float* __restrict__ x, __half* __restrict__ xh,
                          int n4) {
    int i = blockIdx.x * blockDim.x + threadIdx.x;
    if (i < n4) {
        float4 v = reinterpret_cast<const float4*>(x)[i];
        reinterpret_cast<uint2*>(xh)[i] = make_uint2(pack2(v.x, v.y), pack2(v.z, v.w));
    }
}
// Both weight transposes in one launch (blockIdx.z selects the tensor).
// wt[n][k] = (half) w[k][n];  w: [K,N] fp32 row-major
__global__ void transpose_w2(const float* __restrict__ w0, __half* __restrict__ wt0,
                             int K0, int N0,
                             const float* __restrict__ w1, __half* __restrict__ wt1,
                             int K1, int N1) {
    const float* w;  __half* wt;  int K, N;
    if (blockIdx.z == 0) { w = w0; wt = wt0; K = K0; N = N0; }
    else                 { w = w1; wt = wt1; K = K1; N = N1; }
    const int n0 = blockIdx.x * 32, k0 = blockIdx.y * 32;
    if (n0 >= N || k0 >= K) return;
    __shared__ __half t[32][33];
    const int tx = threadIdx.x, ty = threadIdx.y;
    #pragma unroll
    for (int j = 0; j < 32; j += 8)
        t[ty + j][tx] = __float2half(w[(size_t)(k0 + ty + j) * N + n0 + tx]);
    __syncthreads();
    #pragma unroll
    for (int j = 0; j < 32; j += 8)
        wt[(size_t)(n0 + ty + j) * K + k0 + tx] = t[tx][ty + j];
}

// ---------------------------------------------------------------------------
// gemm_cp: round-9 known-good.  C[M,N] = A[M,K] @ Bt[N,K]^T, fp16 K-major.
// 128x128 CTA tile, BK=32, 4-stage cp.async, 128 threads = 4 warps (2x2),
// warp tile 64x64.
// ---------------------------------------------------------------------------
#define GSTAGE 20480
#define GEMM_SMEM (4 * GSTAGE)

template <typename TC>
__global__ __launch_bounds__(128, 2) void gemm_cp(
    const __half* __restrict__ A, const __half* __restrict__ Bt,
    TC* __restrict__ Cm, int M, int N, int K)
{
    extern __shared__ __align__(128) char smem[];
    uint32_t sb;
    asm("{ .reg .u64 t; cvta.to.shared.u64 t, %1; cvt.u32.u64 %0, t; }"
        : "=r"(sb) : "l"(smem));

    const int tid  = threadIdx.x;
    const int lane = tid & 31;
    const int warp = tid >> 5;
    const int wm = warp >> 1, wn = warp & 1;
    const int g = lane >> 2, t = lane & 3;
    const int m0 = blockIdx.y * 128;
    const int n0 = blockIdx.x * 128;
    const int nk = K >> 5;

    const __half* Abase = A + (size_t)m0 * K;
    const __half* Bbase = Bt + (size_t)n0 * K;

    auto load_chunk = [&](int c, int s) {
        const uint32_t base = sb + s * GSTAGE;
        const __half* Ac = Abase + (size_t)c * 32;
        const __half* Bc = Bbase + (size_t)c * 32;
        #pragma unroll
        for (int i = 0; i < 8; i++) {
            const int id  = tid + 128 * i;
            const int ab  = id >> 9;
            const int r   = (id >> 2) & 127;
            const int c16 = id & 3;
            const uint32_t off = ab * 10240u + (uint32_t)r * 80 + c16 * 16;
            const __half* src = (ab ? Bc : Ac) + (size_t)r * K + c16 * 8;
            cpa16(base + off, src);
        }
        CP_COMMIT();
    };

    uint32_t aAddr[4], bAddr[4];
    #pragma unroll
    for (int mt = 0; mt < 4; mt++)
        aAddr[mt] = sb + (wm * 64 + mt * 16 + (lane & 15)) * 80
                       + ((lane >> 4) * 8) * 2;
    #pragma unroll
    for (int ntp = 0; ntp < 4; ntp++)
        bAddr[ntp] = sb + 10240
                   + (wn * 64 + ntp * 16 + ((lane >> 4) & 1) * 8 + (lane & 7)) * 80
                   + (((lane >> 3) & 1) * 8) * 2;

    load_chunk(0, 0); load_chunk(1, 1); load_chunk(2, 2);

    float acc[4][8][4];
    #pragma unroll
    for (int mt = 0; mt < 4; mt++)
        #pragma unroll
        for (int nt = 0; nt < 8; nt++)
            #pragma unroll
            for (int j = 0; j < 4; j++) acc[mt][nt][j] = 0.f;

    for (int kt = 0; kt < nk; kt++) {
        const int s = kt & 3;
        if (kt < nk - 2)       CP_WAIT2();
        else if (kt == nk - 2) CP_WAIT1();
        else                   CP_WAIT0();
        __syncthreads();
        if (kt + 3 < nk) load_chunk(kt + 3, (kt + 3) & 3);

        const uint32_t so = (uint32_t)s * GSTAGE;
        #pragma unroll
        for (int kk = 0; kk < 2; kk++) {
            const uint32_t ko = kk * 32;
            uint32_t af[4][4], bf[4][4];
            #pragma unroll
            for (int mt = 0; mt < 4; mt++)
                ldm_x4(af[mt], aAddr[mt] + so + ko);
            #pragma unroll
            for (int ntp = 0; ntp < 4; ntp++)
                ldm_x4(bf[ntp], bAddr[ntp] + so + ko);
            #pragma unroll
            for (int mt = 0; mt < 4; mt++)
                #pragma unroll
                for (int nt = 0; nt < 8; nt++)
                    mma_f16(acc[mt][nt], af[mt], &bf[nt >> 1][(nt & 1) * 2]);
        }
    }

    #pragma unroll
    for (int mt = 0; mt < 4; mt++) {
        const int r0 = m0 + wm * 64 + mt * 16 + g;
        #pragma unroll
        for (int nt = 0; nt < 8; nt++) {
            const int c0 = n0 + wn * 64 + nt * 8 + 2 * t;
            if (sizeof(TC) == 2) {
                *reinterpret_cast<__half2*>((__half*)Cm + (size_t)r0 * N + c0) =
                    __floats2half2_rn(acc[mt][nt][0], acc[mt][nt][1]);
                *reinterpret_cast<__half2*>((__half*)Cm + (size_t)(r0 + 8) * N + c0) =
                    __floats2half2_rn(acc[mt][nt][2], acc[mt][nt][3]);
            } else {
                *reinterpret_cast<float2*>((float*)Cm + (size_t)r0 * N + c0) =
                    make_float2(acc[mt][nt][0], acc[mt][nt][1]);
                *reinterpret_cast<float2*>((float*)Cm + (size_t)(r0 + 8) * N + c0) =
                    make_float2(acc[mt][nt][2], acc[mt][nt][3]);
            }
        }
    }
}

// ---------------------------------------------------------------------------
// attn_f16: round-12 algorithm with register trim: only TWO pinned ldmatrix
// base registers (addrK0/addrV0); all kg/ks/dtp offsets are compile-time
// constants folded into short-lived temporaries.  With true state ~124 regs,
// __launch_bounds__(128, 4) should fit spill-free -> 16 warps/SM.
// BQ=64, BKV=64, 4 warps x 16 rows, 3-stage cp.async ring, online softmax
// (log2 domain, ex2.approx.f16x2, packed fp16x2 max reduce, HADD2 lp tree).
// ---------------------------------------------------------------------------
#define KVSTR   72
#define KVROWS  64
#define KVTILE  (KVROWS * KVSTR)
#define KVSTAGE_B (2 * KVTILE * 2)
#define ATTN_SMEM (3 * KVSTAGE_B)       // 55296
#define KG_OFF (16 * KVSTR * 2)         // 2304 bytes between 16-key groups

__global__ __launch_bounds__(128, 4) void attn_f16(
    const __half* __restrict__ qkv, const float* __restrict__ sink,
    __half* __restrict__ y)
{
    extern __shared__ __align__(16) __half KV[];

    const int tid  = threadIdx.x;
    const int lane = tid & 31;
    const int warp = tid >> 5;
    const int g = lane >> 2, t = lane & 3;
    const int qt = (int)gridDim.x - 1 - (int)blockIdx.x;   // longest first
    const int bh = blockIdx.y;
    const int b = bh >> 4, h = bh & 15;
    const int q0 = qt * 64;
    const size_t rowbase = (size_t)b * T_;

    const int rg0 = q0 + warp * 16 + g;
    const int rg1 = rg0 + 8;

    // Q fragments, scale = (1/8)*log2(e) folded in (log2-domain scores)
    uint32_t qa[4][4];
    {
        const __half2 sc = __floats2half2_rn(0.18033688f, 0.18033688f);
        const __half2* qp0 = reinterpret_cast<const __half2*>(
            &qkv[(rowbase + rg0) * QKVN + h * D_]);
        const __half2* qp8 = qp0 + (size_t)8 * QKVN / 2;
        #pragma unroll
        for (int ks = 0; ks < 4; ks++) {
            __half2 v0 = __hmul2(qp0[8 * ks + t], sc);
            __half2 v1 = __hmul2(qp8[8 * ks + t], sc);
            __half2 v2 = __hmul2(qp0[8 * ks + t + 4], sc);
            __half2 v3 = __hmul2(qp8[8 * ks + t + 4], sc);
            qa[ks][0] = *reinterpret_cast<uint32_t*>(&v0);
            qa[ks][1] = *reinterpret_cast<uint32_t*>(&v1);
            qa[ks][2] = *reinterpret_cast<uint32_t*>(&v2);
            qa[ks][3] = *reinterpret_cast<uint32_t*>(&v3);
        }
    }

    // ldmatrix base addresses (stage 0) — only two pinned registers
    uint32_t sbase;
    asm("{ .reg .u64 tt; cvta.to.shared.u64 tt, %1; cvt.u32.u64 %0, tt; }"
        : "=r"(sbase) : "l"(KV));
    uint32_t addrK0, addrV0;
    {
        const int kvK = ((lane >> 4) & 1) * 8 + (lane & 7);
        const int dK  = ((lane >> 3) & 1) * 8;
        addrK0 = sbase + (kvK * KVSTR + dK) * 2;
        const int kvV = ((lane >> 3) & 1) * 8 + (lane & 7);
        const int dV  = ((lane >> 4) & 1) * 8;
        addrV0 = sbase + KVTILE * 2 + (kvV * KVSTR + dV) * 2;
    }

    // KV tile loader: 64 rows x (K+V) = 16KB per stage, 8 x 16B per thread
    auto load_kv = [&](int j, int s) {
        const uint32_t base = sbase + (uint32_t)s * KVSTAGE_B;
        const int j0 = j * 64;
        #pragma unroll
        for (int i = 0; i < 8; i++) {
            const int id = tid + 128 * i;          // 0..1023
            const int kv = id >> 9;                // 0 = K, 1 = V
            const int r  = (id >> 3) & 63;
            const int c16 = id & 7;
            const size_t src = (rowbase + j0 + r) * QKVN
                             + (size_t)(1 + kv) * H_ * D_ + h * D_ + c16 * 8;
            cpa16(base + kv * (KVTILE * 2) + r * (KVSTR * 2) + c16 * 16,
                  &qkv[src]);
        }
        CP_COMMIT();
    };

    // online softmax state (log2 domain; sink: m = sink*log2e)
    float m0v = sink[h] * 1.44269504f, m1v = m0v;
    float lp0 = 0.25f, lp1 = 0.25f;     // quad-sum -> sink l contribution = 1
    float oacc[8][4];
    #pragma unroll
    for (int dt = 0; dt < 8; dt++)
        #pragma unroll
        for (int j = 0; j < 4; j++) oacc[dt][j] = 0.f;

    const int ntile = qt + 1;
    load_kv(0, 0);
    if (ntile > 1) load_kv(1, 1);

    for (int j = 0; j < ntile; j++) {
        const int s = j % 3;
        if (j < ntile - 1) CP_WAIT1(); else CP_WAIT0();
        __syncthreads();
        if (j + 2 < ntile) load_kv(j + 2, (j + 2) % 3);

        const uint32_t so = (uint32_t)s * KVSTAGE_B;
        const uint32_t kb = addrK0 + so;

        // S (log2 domain) = (Q*scale*log2e) . K^T   [16 x 64 per warp]
        float sacc[8][4];
        #pragma unroll
        for (int nt = 0; nt < 8; nt++)
            #pragma unroll
            for (int jj = 0; jj < 4; jj++) sacc[nt][jj] = 0.f;
        #pragma unroll
        for (int ks = 0; ks < 4; ks++) {
            #pragma unroll
            for (int kg = 0; kg < 4; kg++) {
                uint32_t bk[4];
                ldm_x4(bk, kb + kg * KG_OFF + ks * 32);
                mma_f16(sacc[2 * kg],     qa[ks], &bk[0]);
                mma_f16(sacc[2 * kg + 1], qa[ks], &bk[2]);
            }
        }

        // causal mask (diagonal tile only)
        const int j0 = j * 64;
        if (j0 >= q0) {
            #pragma unroll
            for (int nt = 0; nt < 8; nt++) {
                const int cg = j0 + nt * 8 + 2 * t;
                if (cg     > rg0) sacc[nt][0] = -1e30f;
                if (cg + 1 > rg0) sacc[nt][1] = -1e30f;
                if (cg     > rg1) sacc[nt][2] = -1e30f;
                if (cg + 1 > rg1) sacc[nt][3] = -1e30f;
            }
        }

        // row maxima: in-thread fp32, quad-reduce as packed fp16x2 (2 shfl)
        float rmax0 = -1e30f, rmax1 = -1e30f;
        #pragma unroll
        for (int nt = 0; nt < 8; nt++) {
            rmax0 = fmaxf(rmax0, fmaxf(sacc[nt][0], sacc[nt][1]));
            rmax1 = fmaxf(rmax1, fmaxf(sacc[nt][2], sacc[nt][3]));
        }
        uint32_t rmx = pack2(rmax0, rmax1);
        rmx = hmax2u(rmx, __shfl_xor_sync(0xffffffffu, rmx, 1));
        rmx = hmax2u(rmx, __shfl_xor_sync(0xffffffffu, rmx, 2));
        const float2 mx = __half22float2(*reinterpret_cast<__half2*>(&rmx));

        const float mn0 = fmaxf(m0v, mx.x);
        const float mn1 = fmaxf(m1v, mx.y);

        // rescale only when the running max increased (quad-uniform branch)
        if (mn0 > m0v || mn1 > m1v) {
            const float corr0 = exp2_fast(m0v - mn0);
            const float corr1 = exp2_fast(m1v - mn1);
            lp0 *= corr0; lp1 *= corr1;
            #pragma unroll
            for (int dt = 0; dt < 8; dt++) {
                oacc[dt][0] *= corr0; oacc[dt][1] *= corr0;
                oacc[dt][2] *= corr1; oacc[dt][3] *= corr1;
            }
            m0v = mn0; m1v = mn1;
        }

        // P = 2^(S - m) via ex2.approx.f16x2 — results are the A-fragments
        uint32_t pa[4][4];
        #pragma unroll
        for (int kg = 0; kg < 4; kg++) {
            #pragma unroll
            for (int nn = 0; nn < 2; nn++) {
                const int nt = kg * 2 + nn;
                pa[kg][nn * 2 + 0] =
                    ex2h2(pack2(sacc[nt][0] - m0v, sacc[nt][1] - m0v));
                pa[kg][nn * 2 + 1] =
                    ex2h2(pack2(sacc[nt][2] - m1v, sacc[nt][3] - m1v));
            }
        }

        // lp += balanced HADD2 tree (3 levels) + one fp32 convert per row
        {
            uint32_t a0 = hadd2u(pa[0][0], pa[0][2]);
            uint32_t a1 = hadd2u(pa[1][0], pa[1][2]);
            uint32_t a2 = hadd2u(pa[2][0], pa[2][2]);
            uint32_t a3 = hadd2u(pa[3][0], pa[3][2]);
            uint32_t v0 = hadd2u(hadd2u(a0, a1), hadd2u(a2, a3));
            float2 f0 = __half22float2(*reinterpret_cast<__half2*>(&v0));
            lp0 += f0.x + f0.y;

            uint32_t b0 = hadd2u(pa[0][1], pa[0][3]);
            uint32_t b1 = hadd2u(pa[1][1], pa[1][3]);
            uint32_t b2 = hadd2u(pa[2][1], pa[2][3]);
            uint32_t b3 = hadd2u(pa[3][1], pa[3][3]);
            uint32_t v1 = hadd2u(hadd2u(b0, b1), hadd2u(b2, b3));
            float2 f1 = __half22float2(*reinterpret_cast<__half2*>(&v1));
            lp1 += f1.x + f1.y;
        }

        // O += P . V
        const uint32_t vb = addrV0 + so;
        #pragma unroll
        for (int kg = 0; kg < 4; kg++) {
            const uint32_t koff = vb + kg * KG_OFF;
            uint32_t bv[4][4];
            #pragma unroll
            for (int dtp = 0; dtp < 4; dtp++)
                ldm_x4t(bv[dtp], koff + dtp * 32);
            #pragma unroll
            for (int dt = 0; dt < 8; dt++)
                mma_f16(oacc[dt], pa[kg], &bv[dt >> 1][(dt & 1) * 2]);
        }
    }

    // final l reduction (once); sink share exact (scaled through all corrs)
    float l0 = lp0, l1 = lp1;
    l0 += __shfl_xor_sync(0xffffffffu, l0, 1);
    l0 += __shfl_xor_sync(0xffffffffu, l0, 2);
    l1 += __shfl_xor_sync(0xffffffffu, l1, 1);
    l1 += __shfl_xor_sync(0xffffffffu, l1, 2);
    const float inv0 = 1.f / l0, inv1 = 1.f / l1;

    __half2* yp0 = reinterpret_cast<__half2*>(&y[(rowbase + rg0) * C_ + h * D_]);
    __half2* yp1 = reinterpret_cast<__half2*>(&y[(rowbase + rg1) * C_ + h * D_]);
    #pragma unroll
    for (int dt = 0; dt < 8; dt++) {
        yp0[4 * dt + t] = __floats2half2_rn(oacc[dt][0] * inv0, oacc[dt][1] * inv0);
        yp1[4 * dt + t] = __floats2half2_rn(oacc[dt][2] * inv1, oacc[dt][3] * inv1);
    }
}

// ---------------------------------------------------------------------------
extern "C" void kernel_launch(void* const* d_in, const int* in_sizes, int n_in,
                              void* d_out, int out_size)
{
    const float* x      = (const float*)d_in[0];   // [2,2048,1024]
    const float* w_qkv  = (const float*)d_in[1];   // [1024,3072]
    const float* w_proj = (const float*)d_in[2];   // [1024,1024]
    const float* sink   = (const float*)d_in[3];   // [16]
    float* out = (float*)d_out;                    // [4096,1024]

    __half *xh, *wqT, *wpT, *qkv, *yb;
    cudaGetSymbolAddress((void**)&xh,  g_xh);
    cudaGetSymbolAddress((void**)&wqT, g_wqT);
    cudaGetSymbolAddress((void**)&wpT, g_wpT);
    cudaGetSymbolAddress((void**)&qkv, g_qkv);
    cudaGetSymbolAddress((void**)&yb,  g_y);

    cudaFuncSetAttribute(gemm_cp<__half>,
        cudaFuncAttributeMaxDynamicSharedMemorySize, GEMM_SMEM);
    cudaFuncSetAttribute(gemm_cp<float>,
        cudaFuncAttributeMaxDynamicSharedMemorySize, GEMM_SMEM);
    cudaFuncSetAttribute(attn_f16,
        cudaFuncAttributeMaxDynamicSharedMemorySize, ATTN_SMEM);

    // prepass: x -> fp16; both weight transposes fused into one launch
    convert_x<<<(M_ * C_ / 4 + 255) / 256, 256>>>(x, xh, M_ * C_ / 4);
    transpose_w2<<<dim3(QKVN / 32, C_ / 32, 2), dim3(32, 8)>>>(
        w_qkv, wqT, C_, QKVN, w_proj, wpT, C_, C_);

    gemm_cp<__half><<<dim3(QKVN / 128, M_ / 128), 128, GEMM_SMEM>>>(
        xh, wqT, qkv, M_, QKVN, C_);
    attn_f16<<<dim3(T_ / 64, B_ * H_), 128, ATTN_SMEM>>>(qkv, sink, yb);
    gemm_cp<float><<<dim3(C_ / 128, M_ / 128), 128, GEMM_SMEM>>>(
        yb, wpT, out, M_, C_, C_);
}